// round 2
// baseline (speedup 1.0000x reference)
#include <cuda_runtime.h>
#include <cstdint>

#define Bc 1024
#define Sc 1024
#define Fc 36
#define Hc 20
#define Gc 60   // 3*H

typedef unsigned long long u64;

// ---------- packed f32x2 + fast-math helpers ----------
__device__ __forceinline__ u64 pk2(float lo, float hi) {
    u64 r; asm("mov.b64 %0, {%1, %2};" : "=l"(r) : "f"(lo), "f"(hi)); return r;
}
__device__ __forceinline__ void upk2(u64 v, float& lo, float& hi) {
    asm("mov.b64 {%0, %1}, %2;" : "=f"(lo), "=f"(hi) : "l"(v));
}
__device__ __forceinline__ u64 fma2(u64 a, u64 b, u64 c) {
    u64 d; asm("fma.rn.f32x2 %0, %1, %2, %3;" : "=l"(d) : "l"(a), "l"(b), "l"(c)); return d;
}
__device__ __forceinline__ u64 add2(u64 a, u64 b) {
    u64 d; asm("add.rn.f32x2 %0, %1, %2;" : "=l"(d) : "l"(a), "l"(b)); return d;
}
__device__ __forceinline__ float ex2a(float x) { float r; asm("ex2.approx.f32 %0, %1;" : "=f"(r) : "f"(x)); return r; }
__device__ __forceinline__ float rcpa(float x) { float r; asm("rcp.approx.f32 %0, %1;" : "=f"(r) : "f"(x)); return r; }
// sigmoid via ex2/rcp (~1e-6 abs err)
__device__ __forceinline__ float sigm(float x) { return rcpa(1.0f + ex2a(-1.4426950408889634f * x)); }
__device__ __forceinline__ float tanh_(float x) {
    return fmaf(2.0f, rcpa(1.0f + ex2a(-2.8853900817779268f * x)), -1.0f);
}

// 18-feature packed half-dot (9 LDS.128)
__device__ __forceinline__ u64 dot18(const u64* __restrict__ xsh, const u64* w, u64 acc0) {
    const ulonglong2* xp = reinterpret_cast<const ulonglong2*>(xsh);
    u64 a0 = acc0, a1 = 0ULL, a2 = 0ULL, a3 = 0ULL;
#pragma unroll
    for (int k = 0; k < 9; k++) {
        ulonglong2 v = xp[k];
        if ((k & 1) == 0) { a0 = fma2(v.x, w[2*k], a0); a1 = fma2(v.y, w[2*k+1], a1); }
        else              { a2 = fma2(v.x, w[2*k], a2); a3 = fma2(v.y, w[2*k+1], a3); }
    }
    return add2(add2(a0, a2), add2(a1, a3));
}
// 10-feature packed half-dot (5 LDS.128)
__device__ __forceinline__ u64 dot10(const u64* __restrict__ hsh, const u64* w, u64 acc0) {
    const ulonglong2* hp = reinterpret_cast<const ulonglong2*>(hsh);
    u64 a0 = acc0, a1 = 0ULL, a2 = 0ULL, a3 = 0ULL;
#pragma unroll
    for (int k = 0; k < 5; k++) {
        ulonglong2 v = hp[k];
        if ((k & 1) == 0) { a0 = fma2(v.x, w[2*k], a0); a1 = fma2(v.y, w[2*k+1], a1); }
        else              { a2 = fma2(v.x, w[2*k], a2); a3 = fma2(v.y, w[2*k+1], a3); }
    }
    return add2(add2(a0, a2), add2(a1, a3));
}
// 20-feature packed full-dot (for FC)
__device__ __forceinline__ u64 dot20f(const u64* __restrict__ hsh, const u64* w, u64 acc0) {
    const ulonglong2* hp = reinterpret_cast<const ulonglong2*>(hsh);
    u64 a0 = acc0, a1 = 0ULL, a2 = 0ULL, a3 = 0ULL;
#pragma unroll
    for (int k = 0; k < 10; k++) {
        ulonglong2 v = hp[k];
        if ((k & 1) == 0) { a0 = fma2(v.x, w[2*k], a0); a1 = fma2(v.y, w[2*k+1], a1); }
        else              { a2 = fma2(v.x, w[2*k], a2); a3 = fma2(v.y, w[2*k+1], a3); }
    }
    return add2(add2(a0, a2), add2(a1, a3));
}

// ---------- dtype detection: int64 vs int32 onehots ----------
__device__ int g_is64;

__global__ void detect_kernel(const int* __restrict__ oh32) {
    if (threadIdx.x == 0 && blockIdx.x == 0) {
        int odd_zero = 1;
        for (int i = 1; i < 256; i += 2) {
            if (oh32[i] != 0) { odd_zero = 0; break; }
        }
        g_is64 = odd_zero;   // little-endian int64 small values => odd words all zero
    }
}

// ---------- kernel 1: embedding concat -> origin ----------
__global__ void embed_kernel(const float* __restrict__ x, const void* __restrict__ ohraw,
                             const float* __restrict__ e0, const float* __restrict__ e1,
                             const float* __restrict__ e2, const float* __restrict__ e3,
                             float* __restrict__ org)
{
    int idx = blockIdx.x * blockDim.x + threadIdx.x;
    if (idx >= Bc * Sc) return;
    const float4* xr = reinterpret_cast<const float4*>(x + (size_t)idx * 12);
    float4 v0 = xr[0], v1 = xr[1], v2 = xr[2];

    long long i0, i1, i2, i3;
    if (g_is64) {
        const longlong2* op = reinterpret_cast<const longlong2*>((const long long*)ohraw + (size_t)idx * 4);
        longlong2 a = op[0], b = op[1];
        i0 = a.x; i1 = a.y; i2 = b.x; i3 = b.y;
    } else {
        int4 a = *reinterpret_cast<const int4*>((const int*)ohraw + (size_t)idx * 4);
        i0 = a.x; i1 = a.y; i2 = a.z; i3 = a.w;
    }
    // clamp => never OOB even on a wrong dtype guess
    i0 = i0 < 0 ? 0 : (i0 > 9  ? 9  : i0);
    i1 = i1 < 0 ? 0 : (i1 > 19 ? 19 : i1);
    i2 = i2 < 0 ? 0 : (i2 > 49 ? 49 : i2);
    i3 = i3 < 0 ? 0 : (i3 > 99 ? 99 : i3);

    float4* out = reinterpret_cast<float4*>(org + (size_t)idx * 36);
    out[0] = v0; out[1] = v1; out[2] = v2;
    out[3] = *reinterpret_cast<const float4*>(e0 + i0 * 4);
    out[4] = *reinterpret_cast<const float4*>(e1 + i1 * 4);
    const float4* p2 = reinterpret_cast<const float4*>(e2 + i2 * 8);
    out[5] = p2[0]; out[6] = p2[1];
    const float4* p3 = reinterpret_cast<const float4*>(e3 + i3 * 8);
    out[7] = p3[0]; out[8] = p3[1];
}

// ---------- kernel 2: persistent GRU encoder + autoregressive decoder ----------
// 128 threads per block = 2 batch elements packed in f32x2 lanes.
// Gate row r (0..59) is split across threads r (features 0..17 / h 0..9) and
// r+60 (features 18..35 / h 10..19): 28 u64 weight regs per thread, no spills.
// Threads 0..35 also hold the FC row weights (20 u64).
__global__ void __launch_bounds__(128) gru_kernel(
    const float* __restrict__ org,
    const float* __restrict__ Wih1, const float* __restrict__ Whh1,
    const float* __restrict__ bih1, const float* __restrict__ bhh1,
    const float* __restrict__ Wih2, const float* __restrict__ Whh2,
    const float* __restrict__ bih2, const float* __restrict__ bhh2,
    const float* __restrict__ Wfc,  const float* __restrict__ bfc,
    float* __restrict__ xs)
{
    const int j = threadIdx.x;
    const int b0 = blockIdx.x * 2;
    const size_t base0 = (size_t)b0 * Sc * Fc;
    const size_t base1 = base0 + (size_t)Sc * Fc;

    __shared__ __align__(16) u64 xring[4][Fc];  // encoder input ring
    __shared__ __align__(16) u64 hbuf[Hc];
    __shared__ __align__(16) u64 pga[120];      // partial gi (+bias in half0)
    __shared__ __align__(16) u64 pgb[120];      // partial gh (+bias in half0)
    __shared__ __align__(16) u64 xdec[Fc];

    const bool is_gate = (j < 120);
    const int  r    = (j < 60) ? j : j - 60;    // gate row
    const int  half = (j < 60) ? 0 : 1;
    const bool is_h  = (j < Hc);
    const bool is_fc = (j < Fc);
    const int  jp = j - 84;                      // prefetch lane
    const bool is_pf = (jp >= 0) && (jp < Fc);

    u64 wih[18], whh[10], wfc[20];
    u64 ba = 0ULL, bb = 0ULL, bfcp = 0ULL;

    // --- encoder weights ---
    if (is_gate) {
#pragma unroll
        for (int k = 0; k < 18; k++) { float w = Wih1[r * Fc + half * 18 + k]; wih[k] = pk2(w, w); }
#pragma unroll
        for (int k = 0; k < 10; k++) { float w = Whh1[r * Hc + half * 10 + k]; whh[k] = pk2(w, w); }
        if (half == 0) {
            float t1 = bih1[r]; ba = pk2(t1, t1);
            float t2 = bhh1[r]; bb = pk2(t2, t2);
        }
    }
    if (is_h) hbuf[j] = 0ULL;

    float q0 = 0.f, q1 = 0.f;
    if (is_pf) {
        xring[0][jp] = pk2(org[base0 + 0 * Fc + jp], org[base1 + 0 * Fc + jp]);
        xring[1][jp] = pk2(org[base0 + 1 * Fc + jp], org[base1 + 1 * Fc + jp]);
        xring[2][jp] = pk2(org[base0 + 2 * Fc + jp], org[base1 + 2 * Fc + jp]);
        q0 = org[base0 + 3 * Fc + jp];
        q1 = org[base1 + 3 * Fc + jp];
    }
    __syncthreads();

    // ================= encoder: S steps =================
    for (int t = 0; t < Sc; t++) {
        float n0 = 0.f, n1 = 0.f;
        if (is_pf && (t + 4 < Sc)) {
            n0 = org[base0 + (size_t)(t + 4) * Fc + jp];
            n1 = org[base1 + (size_t)(t + 4) * Fc + jp];
        }
        if (is_gate) {
            u64 aa  = dot18(xring[t & 3] + half * 18, wih, ba);
            u64 bbv = dot10(hbuf + half * 10, whh, bb);
            pga[j] = aa; pgb[j] = bbv;
        }
        if (is_pf && (t + 3 < Sc)) xring[(t + 3) & 3][jp] = pk2(q0, q1);
        q0 = n0; q1 = n1;
        __syncthreads();
        if (is_h) {
            u64 gr = add2(add2(pga[j], pga[j + 60]), add2(pgb[j], pgb[j + 60]));
            u64 gz = add2(add2(pga[j + 20], pga[j + 80]), add2(pgb[j + 20], pgb[j + 80]));
            u64 gin = add2(pga[j + 40], pga[j + 100]);
            u64 ghn = add2(pgb[j + 40], pgb[j + 100]);
            float rx, ry, zx, zy, ax, ay, bx, by, hx, hy;
            upk2(gr, rx, ry); upk2(gz, zx, zy);
            upk2(gin, ax, ay); upk2(ghn, bx, by);
            upk2(hbuf[j], hx, hy);
            float r0 = sigm(rx), r1 = sigm(ry);
            float z0 = sigm(zx), z1 = sigm(zy);
            float nn0 = tanh_(fmaf(r0, bx, ax));
            float nn1 = tanh_(fmaf(r1, by, ay));
            hbuf[j] = pk2(fmaf(z0, hx - nn0, nn0), fmaf(z1, hy - nn1, nn1));
        }
        __syncthreads();
    }

    // ================= phase switch =================
    if (is_gate) {
#pragma unroll
        for (int k = 0; k < 18; k++) { float w = Wih2[r * Fc + half * 18 + k]; wih[k] = pk2(w, w); }
#pragma unroll
        for (int k = 0; k < 10; k++) { float w = Whh2[r * Hc + half * 10 + k]; whh[k] = pk2(w, w); }
        if (half == 0) {
            float t1 = bih2[r]; ba = pk2(t1, t1);
            float t2 = bhh2[r]; bb = pk2(t2, t2);
        }
    }
    if (is_fc) {
#pragma unroll
        for (int k = 0; k < Hc; k++) { float w = Wfc[j * Hc + k]; wfc[k] = pk2(w, w); }
        float t3 = bfc[j]; bfcp = pk2(t3, t3);
    }
    if (is_h) {
        float hx, hy; upk2(hbuf[j], hx, hy);
        hbuf[j] = pk2(tanh_(hx), tanh_(hy));
    }
    __syncthreads();

    // x0 = tanh(h @ Wfc.T + bfc) -> xs[:, S-1, :]
    if (is_fc) {
        u64 acc = dot20f(hbuf, wfc, bfcp);
        float xx, xy; upk2(acc, xx, xy);
        xx = tanh_(xx); xy = tanh_(xy);
        xdec[j] = pk2(xx, xy);
        xs[base0 + (size_t)(Sc - 1) * Fc + j] = xx;
        xs[base1 + (size_t)(Sc - 1) * Fc + j] = xy;
    }
    __syncthreads();

    // ================= decoder: S-1 autoregressive steps =================
    for (int k = 1; k < Sc; k++) {
        if (is_gate) {
            u64 aa  = dot18(xdec + half * 18, wih, ba);
            u64 bbv = dot10(hbuf + half * 10, whh, bb);
            pga[j] = aa; pgb[j] = bbv;
        }
        __syncthreads();
        if (is_h) {
            u64 gr = add2(add2(pga[j], pga[j + 60]), add2(pgb[j], pgb[j + 60]));
            u64 gz = add2(add2(pga[j + 20], pga[j + 80]), add2(pgb[j + 20], pgb[j + 80]));
            u64 gin = add2(pga[j + 40], pga[j + 100]);
            u64 ghn = add2(pgb[j + 40], pgb[j + 100]);
            float rx, ry, zx, zy, ax, ay, bx, by, hx, hy;
            upk2(gr, rx, ry); upk2(gz, zx, zy);
            upk2(gin, ax, ay); upk2(ghn, bx, by);
            upk2(hbuf[j], hx, hy);
            float r0 = sigm(rx), r1 = sigm(ry);
            float z0 = sigm(zx), z1 = sigm(zy);
            float nn0 = tanh_(fmaf(r0, bx, ax));
            float nn1 = tanh_(fmaf(r1, by, ay));
            float g0 = fmaf(z0, hx - nn0, nn0);
            float g1 = fmaf(z1, hy - nn1, nn1);
            hbuf[j] = pk2(tanh_(g0), tanh_(g1));   // decoder outer tanh
        }
        __syncthreads();
        if (is_fc) {
            u64 acc = dot20f(hbuf, wfc, bfcp);
            float xx, xy; upk2(acc, xx, xy);
            xx = tanh_(xx); xy = tanh_(xy);
            xdec[j] = pk2(xx, xy);
            const size_t row = (size_t)(Sc - 1 - k) * Fc;
            xs[base0 + row + j] = xx;
            xs[base1 + row + j] = xy;
        }
        __syncthreads();
    }
}

// ---------- launcher ----------
extern "C" void kernel_launch(void* const* d_in, const int* in_sizes, int n_in,
                              void* d_out, int out_size)
{
    const float* x    = (const float*)d_in[0];
    const void*  oh   = d_in[1];
    const float* e0   = (const float*)d_in[2];
    const float* e1   = (const float*)d_in[3];
    const float* e2   = (const float*)d_in[4];
    const float* e3   = (const float*)d_in[5];
    const float* Wih1 = (const float*)d_in[6];
    const float* Whh1 = (const float*)d_in[7];
    const float* bih1 = (const float*)d_in[8];
    const float* bhh1 = (const float*)d_in[9];
    const float* Wih2 = (const float*)d_in[10];
    const float* Whh2 = (const float*)d_in[11];
    const float* bih2 = (const float*)d_in[12];
    const float* bhh2 = (const float*)d_in[13];
    const float* Wfc  = (const float*)d_in[14];
    const float* bfc  = (const float*)d_in[15];

    float* out = (float*)d_out;
    float* org = out;                              // output #1 (origin), also GRU input
    float* xs  = out + (size_t)Bc * Sc * Fc;       // output #2 (decoded, time-flipped)

    detect_kernel<<<1, 1>>>((const int*)oh);
    embed_kernel<<<(Bc * Sc + 127) / 128, 128>>>(x, oh, e0, e1, e2, e3, org);
    gru_kernel<<<Bc / 2, 128>>>(org, Wih1, Whh1, bih1, bhh1,
                                Wih2, Whh2, bih2, bhh2, Wfc, bfc, xs);
}